// round 14
// baseline (speedup 1.0000x reference)
#include <cuda_runtime.h>
#include <math.h>

#define NRAYS 2048
#define TOT 128
#define INDS 16
#define HID 64
#define MTOT (NRAYS*TOT)
#define EPSF 1e-8f

typedef unsigned long long u64;

// ---------------- f32x2 packed helpers (sm_103a) ----------------
__device__ __forceinline__ u64 pk2(float lo, float hi) {
    u64 r; asm("mov.b64 %0, {%1,%2};" : "=l"(r) : "f"(lo), "f"(hi)); return r;
}
__device__ __forceinline__ u64 bc2(float v) {
    u64 r; asm("mov.b64 %0, {%1,%1};" : "=l"(r) : "f"(v)); return r;
}
__device__ __forceinline__ void upk2(u64 a, float& lo, float& hi) {
    asm("mov.b64 {%0,%1}, %2;" : "=f"(lo), "=f"(hi) : "l"(a));
}
__device__ __forceinline__ u64 fma2(u64 a, u64 b, u64 c) {
    u64 d; asm("fma.rn.f32x2 %0, %1, %2, %3;" : "=l"(d) : "l"(a), "l"(b), "l"(c)); return d;
}
__device__ __forceinline__ u64 mul2(u64 a, u64 b) {
    u64 d; asm("mul.rn.f32x2 %0, %1, %2;" : "=l"(d) : "l"(a), "l"(b)); return d;
}

// MUFU sin pair: 2 SFU-pipe instructions, zero FMA-pipe cost.
__device__ __forceinline__ u64 sin2_mufu(u64 x) {
    float lo, hi; upk2(x, lo, hi);
    return pk2(__sinf(lo), __sinf(hi));
}

// ---------------- scalar helpers (fast-math epilogue) ----------------
__device__ __forceinline__ float tanh_fast(float x) {
    float ax = fminf(fabsf(x), 10.0f);
    float e = __expf(2.0f * ax);
    float t = __fdividef(e - 1.0f, e + 1.0f);
    return (x < 0.0f) ? -t : t;
}
__device__ __forceinline__ float softplus_fast(float x) {
    return fmaxf(x, 0.0f) + __logf(1.0f + __expf(-fabsf(x)));
}
__device__ __forceinline__ float sigmoid_fast(float x) {
    float e = __expf(-fabsf(x));
    float r = __fdividef(1.0f, 1.0f + e);
    return (x >= 0.0f) ? r : (1.0f - r);
}

// ---------------- env map bilinear sample ----------------
__device__ __forceinline__ void sample_env(const float* __restrict__ env,
                                           float px, float py, float pz,
                                           float& Le0, float& Le1, float& Le2) {
    const float INV_PI = 0.3183098861837907f;
    float theta = atan2f(px, -pz);
    if (isnan(theta)) theta = 0.0f;
    theta *= INV_PI;
    float ac = acosf(py);
    if (isnan(ac)) ac = 0.0f;
    float phi = fmaf(ac, 2.0f * INV_PI, -1.0f);

    float ix = ((theta + 1.0f) * 256.0f - 1.0f) * 0.5f;
    float iy = ((phi   + 1.0f) * 128.0f - 1.0f) * 0.5f;
    float x0 = floorf(ix), y0 = floorf(iy);
    float wx = ix - x0,    wy = iy - y0;

    float v0 = 0.0f, v1 = 0.0f, v2 = 0.0f;
    #pragma unroll
    for (int t = 0; t < 4; t++) {
        float xc = x0 + (float)(t & 1);
        float yc = y0 + (float)(t >> 1);
        float w = ((t & 1) ? wx : (1.0f - wx)) * ((t >> 1) ? wy : (1.0f - wy));
        bool inb = (xc >= 0.0f) && (xc < 256.0f) && (yc >= 0.0f) && (yc < 128.0f);
        float wi = inb ? w : 0.0f;
        int xi = (int)fminf(fmaxf(xc, 0.0f), 255.0f);
        int yi = (int)fminf(fmaxf(yc, 0.0f), 127.0f);
        int base = yi * 256 + xi;
        v0 = fmaf(wi, env[base],         v0);
        v1 = fmaf(wi, env[32768 + base], v1);
        v2 = fmaf(wi, env[65536 + base], v2);
    }
    Le0 = __expf(v0); Le1 = __expf(v1); Le2 = __expf(v2);
}

__device__ __forceinline__ u64 dup_bits(float v) {
    u64 b = (u64)__float_as_uint(v);
    return b | (b << 32);
}

// ---------------- main fused renderer ----------------
// 1 block = 1 ray, 256 threads: thread s handles samples 0..7 of sample-slot
// s; thread s+128 handles samples 8..15. Each sample is computed entirely
// within one thread (numerics identical to the 128-thread version); only the
// per-channel raw max (3 floats) crosses threads. Halved per-thread register
// state -> 6 warps/SMSP with unroll-2 software pipelining of the MUFU loop.
__global__ __launch_bounds__(2*TOT, 3)
void nerf_render_kernel(
    const float* __restrict__ rays_o, const float* __restrict__ rays_d,
    const float* __restrict__ env,
    const float* __restrict__ gWd1, const float* __restrict__ gWd2,
    const float* __restrict__ gWf1, const float* __restrict__ gWs,
    const float* __restrict__ gWdir, const float* __restrict__ gWrho,
    const float* __restrict__ jitter, const float* __restrict__ u_t,
    const float* __restrict__ u_scatter, const int* __restrict__ channel,
    float* __restrict__ out)
{
    __shared__ float4 sA[HID];          // Wd1 col j: ax, ay, az, 0
    __shared__ ulonglong2 sBxy[HID];    // Wd2 row j: bx dup, by dup
    __shared__ u64 sBz[HID];            // Wd2 row j: bz dup
    __shared__ float2 sBS[HID];         // depth-0 block-uniform {base_j, slope_j}
    __shared__ float4 sUC[HID][2];      // depth-0 uniform sincos(u) for AA pairs 6,7
    __shared__ float4 sF0[HID];         // Wf1 col j, elems 0..3
    __shared__ float2 sF1[HID];         // Wf1 col j, elems 4..5
    __shared__ float4 sO0[HID];         // Ws[j][0..2], Wdir[j][0]
    __shared__ float4 sO1[HID];         // Wdir[j][1..2], Wrho[j][0..1]
    __shared__ float  sO2[HID];         // Wrho[j][2]
    __shared__ float4 sRM[TOT];         // high-half raw maxima {rm0,rm1,rm2,-}
    __shared__ float4 sODa[TOT];        // dep-1 state publish: ox,oy,oz,dx
    __shared__ float2 sODb[TOT];        // dep-1 state publish: dy,dz
    __shared__ float  red[4][3];

    int tid = threadIdx.x;
    int s = tid & (TOT - 1);
    int half = tid >> 7;                 // 0: samples 0..7, 1: samples 8..15

    if (tid < HID) {
        int j = tid;
        sA[j]   = make_float4(gWd1[j], gWd1[64 + j], gWd1[128 + j], 0.0f);
        sBxy[j] = make_ulonglong2(dup_bits(gWd2[j * 3]), dup_bits(gWd2[j * 3 + 1]));
        sBz[j]  = dup_bits(gWd2[j * 3 + 2]);
        sF0[j] = make_float4(gWf1[j], gWf1[64 + j], gWf1[128 + j], gWf1[192 + j]);
        sF1[j] = make_float2(gWf1[256 + j], gWf1[320 + j]);
        sO0[j] = make_float4(gWs[j * 3], gWs[j * 3 + 1], gWs[j * 3 + 2], gWdir[j * 3]);
        sO1[j] = make_float4(gWdir[j * 3 + 1], gWdir[j * 3 + 2], gWrho[j * 3], gWrho[j * 3 + 1]);
        sO2[j] = gWrho[j * 3 + 2];
    }
    __syncthreads();

    int ray = blockIdx.x;
    int m = ray * TOT + s;

    float ox = rays_o[ray * 3 + 0], oy = rays_o[ray * 3 + 1], oz = rays_o[ray * 3 + 2];
    float dx = rays_d[ray * 3 + 0], dy = rays_d[ray * 3 + 1], dz = rays_d[ray * 3 + 2];
    bool alive = true;
    float thr0 = 1.0f, thr1 = 1.0f, thr2 = 1.0f;
    float rgb0 = 0.0f, rgb1 = 0.0f, rgb2 = 0.0f;

    // packed AA constants (dep-0 tiny-angle polys)
    u64 cone  = bc2(1.0f);
    u64 cm16  = bc2(-0.16666667f);
    u64 cmh   = bc2(-0.5f);

    #pragma unroll
    for (int dep = 0; dep < 2; ++dep) {
        if (dep == 1 && half == 1) {
            // read the low thread's post-depth-0 state (published below)
            float4 a4 = sODa[s]; float2 b2 = sODb[s];
            ox = a4.x; oy = a4.y; oz = a4.z; dx = a4.w; dy = b2.x; dz = b2.y;
        }

        // sphere intersection (identical on both halves)
        float a = dx * dx + dy * dy + dz * dz;
        float b = 2.0f * (dx * ox + dy * oy + dz * oz);
        float c = ox * ox + oy * oy + oz * oz - 1.0f;
        float delta = b * b - 4.0f * a * c;
        alive = alive && (delta > 0.0f);
        float sq = sqrtf(fmaxf(delta, 0.0f));
        float twoa = 2.0f * a;
        float nears = fmaxf((-b - sq) / twoa, 0.001f);
        float fars  = fmaxf((-b + sq) / twoa, 0.001f);
        float span = fars - nears;

        // Depth-0 block-uniform precomputes
        if (dep == 0) {
            if (tid < HID) {
                float4 aa = sA[tid];
                float base  = fmaf(ox, aa.x, fmaf(oy, aa.y, oz * aa.z));
                float slope = fmaf(dx, aa.x, fmaf(dy, aa.y, dz * aa.z));
                sBS[tid] = make_float2(base, slope);
            }
            __syncthreads();
            if (tid < 2 * HID) {
                int j = tid >> 1;
                int q2 = tid & 1;                  // 0 -> pair 6, 1 -> pair 7
                float2 bs = sBS[j];
                int s0 = 12 + 2 * q2;
                float u0 = fmaf(bs.y, fmaf(span, (float)(s0)     * (1.0f/15.0f), nears), bs.x);
                float u1 = fmaf(bs.y, fmaf(span, (float)(s0 + 1) * (1.0f/15.0f), nears), bs.x);
                sUC[j][q2] = make_float4(__sinf(u0), __sinf(u1), __cosf(u0), __cosf(u1));
            }
            __syncthreads();
        }

        // ---- this thread's 8 samples (2 quads, 4 packed pairs) ----
        const float4* jp = (const float4*)(jitter + (size_t)dep * (size_t)MTOT * INDS
                                                  + (size_t)m * INDS);
        u64 Zp[4];
        u64 jv[2];
        {
            float K = span * (1.0f / 16.0f);
            #pragma unroll
            for (int qq = 0; qq < 2; qq++) {
                int q = 2 * half + qq;
                float4 jvq = jp[q];
                float z0 = nears + span * ((float)(4*q + 0) * (1.0f/15.0f)) + (jvq.x - 0.5f) * K;
                float z1 = nears + span * ((float)(4*q + 1) * (1.0f/15.0f)) + (jvq.y - 0.5f) * K;
                float z2 = nears + span * ((float)(4*q + 2) * (1.0f/15.0f)) + (jvq.z - 0.5f) * K;
                float z3 = nears + span * ((float)(4*q + 3) * (1.0f/15.0f)) + (jvq.w - 0.5f) * K;
                Zp[2*qq]     = pk2(z0, z1);
                Zp[2*qq + 1] = pk2(z2, z3);
                if (qq == 1) {   // only meaningful for half==1, dep==0 (AA pairs)
                    jv[0] = pk2((jvq.x - 0.5f) * K, (jvq.y - 0.5f) * K);
                    jv[1] = pk2((jvq.z - 0.5f) * K, (jvq.w - 0.5f) * K);
                }
            }
        }

        u64 Acc[4][3];
        #pragma unroll
        for (int p = 0; p < 4; p++) { Acc[p][0] = 0; Acc[p][1] = 0; Acc[p][2] = 0; }

        if (dep == 0) {
            if (half == 0) {
                // global pairs 0..3: all MUFU
                #pragma unroll 2
                for (int j = 0; j < HID; j++) {
                    float2 bs = sBS[j];
                    u64 base2  = bc2(bs.x);
                    u64 slope2 = bc2(bs.y);
                    ulonglong2 bxy = sBxy[j];
                    u64 bz = sBz[j];
                    u64 H[4];
                    #pragma unroll
                    for (int p = 0; p < 4; p++)
                        H[p] = sin2_mufu(fma2(Zp[p], slope2, base2));
                    #pragma unroll
                    for (int p = 0; p < 4; p++) {
                        Acc[p][0] = fma2(H[p], bxy.x, Acc[p][0]);
                        Acc[p][1] = fma2(H[p], bxy.y, Acc[p][1]);
                        Acc[p][2] = fma2(H[p], bz,    Acc[p][2]);
                    }
                }
            } else {
                // global pairs 4,5: MUFU; pairs 6,7: angle addition (zero MUFU)
                #pragma unroll 2
                for (int j = 0; j < HID; j++) {
                    float2 bs = sBS[j];
                    u64 base2  = bc2(bs.x);
                    u64 slope2 = bc2(bs.y);
                    ulonglong2 bxy = sBxy[j];
                    u64 bz = sBz[j];
                    u64 H[4];
                    H[0] = sin2_mufu(fma2(Zp[0], slope2, base2));
                    H[1] = sin2_mufu(fma2(Zp[1], slope2, base2));
                    #pragma unroll
                    for (int q2 = 0; q2 < 2; q2++) {
                        float4 uc = sUC[j][q2];
                        u64 su2 = pk2(uc.x, uc.y);
                        u64 cu2 = pk2(uc.z, uc.w);
                        u64 v    = mul2(jv[q2], slope2);
                        u64 s2   = mul2(v, v);
                        u64 sinv = mul2(v, fma2(s2, cm16, cone));
                        u64 cosv = fma2(s2, cmh, cone);
                        H[2 + q2] = fma2(cu2, sinv, mul2(su2, cosv));
                    }
                    #pragma unroll
                    for (int p = 0; p < 4; p++) {
                        Acc[p][0] = fma2(H[p], bxy.x, Acc[p][0]);
                        Acc[p][1] = fma2(H[p], bxy.y, Acc[p][1]);
                        Acc[p][2] = fma2(H[p], bz,    Acc[p][2]);
                    }
                }
            }
        } else {
            // depth 1: per-thread base/slope, all MUFU
            #pragma unroll 2
            for (int j = 0; j < HID; j++) {
                float4 aa = sA[j];
                float base  = fmaf(ox, aa.x, fmaf(oy, aa.y, oz * aa.z));
                float slope = fmaf(dx, aa.x, fmaf(dy, aa.y, dz * aa.z));
                u64 base2  = bc2(base);
                u64 slope2 = bc2(slope);
                ulonglong2 bxy = sBxy[j];
                u64 bz = sBz[j];
                u64 H[4];
                #pragma unroll
                for (int p = 0; p < 4; p++)
                    H[p] = sin2_mufu(fma2(Zp[p], slope2, base2));
                #pragma unroll
                for (int p = 0; p < 4; p++) {
                    Acc[p][0] = fma2(H[p], bxy.x, Acc[p][0]);
                    Acc[p][1] = fma2(H[p], bxy.y, Acc[p][1]);
                    Acc[p][2] = fma2(H[p], bz,    Acc[p][2]);
                }
            }
        }

        // per-thread raw max over this thread's 8 samples
        float rm0 = -1e30f, rm1 = -1e30f, rm2 = -1e30f;
        #pragma unroll
        for (int p = 0; p < 4; p++) {
            float pa, pb;
            upk2(Acc[p][0], pa, pb); rm0 = fmaxf(rm0, fmaxf(pa, pb));
            upk2(Acc[p][1], pa, pb); rm1 = fmaxf(rm1, fmaxf(pa, pb));
            upk2(Acc[p][2], pa, pb); rm2 = fmaxf(rm2, fmaxf(pa, pb));
        }
        if (half == 1)
            sRM[s] = make_float4(rm0, rm1, rm2, 0.0f);
        __syncthreads();

        if (half == 0) {
            float4 o = sRM[s];
            rm0 = fmaxf(rm0, o.x);
            rm1 = fmaxf(rm1, o.y);
            rm2 = fmaxf(rm2, o.z);

            float mm0 = fmaxf(softplus_fast(rm0), 0.001f);
            float mm1 = fmaxf(softplus_fast(rm1), 0.001f);
            float mm2 = fmaxf(softplus_fast(rm2), 0.001f);
            float maxm = fmaxf(mm0, fmaxf(mm1, mm2));

            int ch = 0;
            float maj = 0.001f;
            float t;
            if (dep == 0) {
                ch = channel[m];
                maj = (ch == 0) ? mm0 : ((ch == 1) ? mm1 : mm2);
                float ut = u_t[m];
                t = -log1pf(-ut) / maj + nears;   // keep accurate: decides `hit`
            } else {
                t = fars;
            }
            bool hit = alive && (t >= fars);

            float dn0 = __expf(-mm0 * span) / (maxm + EPSF) + EPSF;
            float dn1 = __expf(-mm1 * span) / (maxm + EPSF) + EPSF;
            float dn2 = __expf(-mm2 * span) / (maxm + EPSF) + EPSF;
            float dmean = (dn0 + dn1 + dn2) * (1.0f / 3.0f);

            float Le0, Le1, Le2;
            sample_env(env, fmaf(dx, fars, ox), fmaf(dy, fars, oy), fmaf(dz, fars, oz),
                       Le0, Le1, Le2);

            if (hit) {
                rgb0 += thr0 * (dn0 / dmean) * Le0;
                rgb1 += thr1 * (dn1 / dmean) * Le1;
                rgb2 += thr2 * (dn2 / dmean) * Le2;
            }
            alive = alive && !hit;

            if (dep == 0) {
                float tr0 = __expf(-mm0 * (t - nears)) / maxm;
                float tr1 = __expf(-mm1 * (t - nears)) / maxm;
                float tr2 = __expf(-mm2 * (t - nears)) / maxm;
                float den2 = (mm0 * tr0 + mm1 * tr1 + mm2 * tr2) * (1.0f / 3.0f);
                if (alive) {
                    thr0 = thr0 * tr0 / den2;
                    thr1 = thr1 * tr1 / den2;
                    thr2 = thr2 * tr2 / den2;
                    ox = fmaf(dx, t, ox);
                    oy = fmaf(dy, t, oy);
                    oz = fmaf(dz, t, oz);
                }
                // material MLP on [o, d] (post-update o)
                float st0 = 0.0f, st1 = 0.0f, st2 = 0.0f;
                float v0 = 0.0f, v1 = 0.0f, v2 = 0.0f;
                float rh0 = 0.0f, rh1 = 0.0f, rh2 = 0.0f;
                #pragma unroll 8
                for (int j = 0; j < HID; j++) {
                    float4 w0 = sF0[j];
                    float2 w1 = sF1[j];
                    float u = fmaf(ox, w0.x, fmaf(oy, w0.y, fmaf(oz, w0.z,
                              fmaf(dx, w0.w, fmaf(dy, w1.x, dz * w1.y)))));
                    float f = tanh_fast(u);
                    float4 p0 = sO0[j];
                    float4 p1 = sO1[j];
                    float p2 = sO2[j];
                    st0 = fmaf(f, p0.x, st0);
                    st1 = fmaf(f, p0.y, st1);
                    st2 = fmaf(f, p0.z, st2);
                    v0  = fmaf(f, p0.w, v0);
                    v1  = fmaf(f, p1.x, v1);
                    v2  = fmaf(f, p1.y, v2);
                    rh0 = fmaf(f, p1.z, rh0);
                    rh1 = fmaf(f, p1.w, rh1);
                    rh2 = fmaf(f, p2,   rh2);
                }
                st0 = softplus_fast(st0);
                st1 = softplus_fast(st1);
                st2 = softplus_fast(st2);
                float nrm = sqrtf(v0 * v0 + v1 * v1 + v2 * v2);
                float invn = 1.0f / (nrm + EPSF);
                float do0 = v0 * invn, do1 = v1 * invn, do2 = v2 * invn;
                float rho0 = sigmoid_fast(rh0), rho1 = sigmoid_fast(rh1), rho2 = sigmoid_fast(rh2);

                float stch = (ch == 0) ? st0 : ((ch == 1) ? st1 : st2);
                float sp = fminf(stch / maj, 1.0f);
                float us = u_scatter[m];
                bool sm = alive && (us < sp);
                if (sm) {
                    dx = do0; dy = do1; dz = do2;
                    thr0 = thr0 / (sp + EPSF) * rho0;
                    thr1 = thr1 / (sp + EPSF) * rho1;
                    thr2 = thr2 / (sp + EPSF) * rho2;
                } else if (alive) {
                    float inv = 1.0f / (1.0f - sp + EPSF);
                    thr0 *= inv; thr1 *= inv; thr2 *= inv;
                }
                // publish post-depth-0 state for the high-half partner
                sODa[s] = make_float4(ox, oy, oz, dx);
                sODb[s] = make_float2(dy, dz);
            }
        }
        __syncthreads();   // sOD visible for dep 1; sRM safe to reuse
    }

    // block reduce: mean over TOT samples of this ray (low half holds rgb)
    if (tid < TOT) {
        #pragma unroll
        for (int off = 16; off > 0; off >>= 1) {
            rgb0 += __shfl_down_sync(0xffffffffu, rgb0, off);
            rgb1 += __shfl_down_sync(0xffffffffu, rgb1, off);
            rgb2 += __shfl_down_sync(0xffffffffu, rgb2, off);
        }
        if ((tid & 31) == 0) {
            red[tid >> 5][0] = rgb0;
            red[tid >> 5][1] = rgb1;
            red[tid >> 5][2] = rgb2;
        }
    }
    __syncthreads();
    if (tid == 0) {
        float a0 = red[0][0] + red[1][0] + red[2][0] + red[3][0];
        float a1 = red[0][1] + red[1][1] + red[2][1] + red[3][1];
        float a2 = red[0][2] + red[1][2] + red[2][2] + red[3][2];
        out[ray * 3 + 0] = a0 * (1.0f / (float)TOT);
        out[ray * 3 + 1] = a1 * (1.0f / (float)TOT);
        out[ray * 3 + 2] = a2 * (1.0f / (float)TOT);
    }
}

extern "C" void kernel_launch(void* const* d_in, const int* in_sizes, int n_in,
                              void* d_out, int out_size) {
    const float* rays_o    = (const float*)d_in[0];
    const float* rays_d    = (const float*)d_in[1];
    const float* env       = (const float*)d_in[2];
    const float* Wd1       = (const float*)d_in[3];
    const float* Wd2       = (const float*)d_in[4];
    const float* Wf1       = (const float*)d_in[5];
    const float* Ws        = (const float*)d_in[6];
    const float* Wdir      = (const float*)d_in[7];
    const float* Wrho      = (const float*)d_in[8];
    const float* jitter    = (const float*)d_in[9];
    const float* u_t       = (const float*)d_in[10];
    const float* u_scatter = (const float*)d_in[11];
    const int*   channel   = (const int*)d_in[12];
    float* out = (float*)d_out;

    nerf_render_kernel<<<NRAYS, 2 * TOT>>>(rays_o, rays_d, env, Wd1, Wd2, Wf1, Ws,
                                           Wdir, Wrho, jitter, u_t, u_scatter,
                                           channel, out);
}

// round 15
// speedup vs baseline: 1.0495x; 1.0495x over previous
#include <cuda_runtime.h>
#include <math.h>

#define NRAYS 2048
#define TOT 128
#define INDS 16
#define HID 64
#define MTOT (NRAYS*TOT)
#define EPSF 1e-8f

typedef unsigned long long u64;

// ---------------- f32x2 packed helpers (sm_103a) ----------------
__device__ __forceinline__ u64 pk2(float lo, float hi) {
    u64 r; asm("mov.b64 %0, {%1,%2};" : "=l"(r) : "f"(lo), "f"(hi)); return r;
}
__device__ __forceinline__ u64 bc2(float v) {
    u64 r; asm("mov.b64 %0, {%1,%1};" : "=l"(r) : "f"(v)); return r;
}
__device__ __forceinline__ void upk2(u64 a, float& lo, float& hi) {
    asm("mov.b64 {%0,%1}, %2;" : "=f"(lo), "=f"(hi) : "l"(a));
}
__device__ __forceinline__ u64 fma2(u64 a, u64 b, u64 c) {
    u64 d; asm("fma.rn.f32x2 %0, %1, %2, %3;" : "=l"(d) : "l"(a), "l"(b), "l"(c)); return d;
}
__device__ __forceinline__ u64 mul2(u64 a, u64 b) {
    u64 d; asm("mul.rn.f32x2 %0, %1, %2;" : "=l"(d) : "l"(a), "l"(b)); return d;
}

// MUFU sin pair: 2 SFU-pipe instructions, zero FMA-pipe cost.
__device__ __forceinline__ u64 sin2_mufu(u64 x) {
    float lo, hi; upk2(x, lo, hi);
    return pk2(__sinf(lo), __sinf(hi));
}

// ---------------- scalar helpers (fast-math epilogue) ----------------
__device__ __forceinline__ float tanh_fast(float x) {
    float ax = fminf(fabsf(x), 10.0f);
    float e = __expf(2.0f * ax);
    float t = __fdividef(e - 1.0f, e + 1.0f);
    return (x < 0.0f) ? -t : t;
}
__device__ __forceinline__ float softplus_fast(float x) {
    return fmaxf(x, 0.0f) + __logf(1.0f + __expf(-fabsf(x)));
}
__device__ __forceinline__ float sigmoid_fast(float x) {
    float e = __expf(-fabsf(x));
    float r = __fdividef(1.0f, 1.0f + e);
    return (x >= 0.0f) ? r : (1.0f - r);
}

// ---------------- env map bilinear sample ----------------
__device__ __forceinline__ void sample_env(const float* __restrict__ env,
                                           float px, float py, float pz,
                                           float& Le0, float& Le1, float& Le2) {
    const float INV_PI = 0.3183098861837907f;
    float theta = atan2f(px, -pz);
    if (isnan(theta)) theta = 0.0f;
    theta *= INV_PI;
    float ac = acosf(py);
    if (isnan(ac)) ac = 0.0f;
    float phi = fmaf(ac, 2.0f * INV_PI, -1.0f);

    float ix = ((theta + 1.0f) * 256.0f - 1.0f) * 0.5f;
    float iy = ((phi   + 1.0f) * 128.0f - 1.0f) * 0.5f;
    float x0 = floorf(ix), y0 = floorf(iy);
    float wx = ix - x0,    wy = iy - y0;

    float v0 = 0.0f, v1 = 0.0f, v2 = 0.0f;
    #pragma unroll
    for (int t = 0; t < 4; t++) {
        float xc = x0 + (float)(t & 1);
        float yc = y0 + (float)(t >> 1);
        float w = ((t & 1) ? wx : (1.0f - wx)) * ((t >> 1) ? wy : (1.0f - wy));
        bool inb = (xc >= 0.0f) && (xc < 256.0f) && (yc >= 0.0f) && (yc < 128.0f);
        float wi = inb ? w : 0.0f;
        int xi = (int)fminf(fmaxf(xc, 0.0f), 255.0f);
        int yi = (int)fminf(fmaxf(yc, 0.0f), 127.0f);
        int base = yi * 256 + xi;
        v0 = fmaf(wi, env[base],         v0);
        v1 = fmaf(wi, env[32768 + base], v1);
        v2 = fmaf(wi, env[65536 + base], v2);
    }
    Le0 = __expf(v0); Le1 = __expf(v1); Le2 = __expf(v2);
}

__device__ __forceinline__ u64 dup_bits(float v) {
    u64 b = (u64)__float_as_uint(v);
    return b | (b << 32);
}

// ---------------- main fused renderer: 1 block = 1 ray, 1 thread = 1 sample ----------------
// Aggregate pipe balance across both depths: dep-1 is all-MUFU (128 cyc/j)
// vs FMA 64, so dep-0 takes MORE angle-addition work: 4 of 8 pairs via AA
// (uniform sincos table), 4 via MUFU. Aggregate per j-pair: FMA 176 cyc,
// MUFU 192 cyc (was 152/224). Unroll-2 software pipelining retained.
__global__ __launch_bounds__(TOT, 4)
void nerf_render_kernel(
    const float* __restrict__ rays_o, const float* __restrict__ rays_d,
    const float* __restrict__ env,
    const float* __restrict__ gWd1, const float* __restrict__ gWd2,
    const float* __restrict__ gWf1, const float* __restrict__ gWs,
    const float* __restrict__ gWdir, const float* __restrict__ gWrho,
    const float* __restrict__ jitter, const float* __restrict__ u_t,
    const float* __restrict__ u_scatter, const int* __restrict__ channel,
    float* __restrict__ out)
{
    __shared__ float4 sA[HID];          // Wd1 col j: ax, ay, az, 0
    __shared__ ulonglong2 sBxy[HID];    // Wd2 row j: bx dup, by dup
    __shared__ u64 sBz[HID];            // Wd2 row j: bz dup
    __shared__ float2 sBS[HID];         // depth-0 block-uniform {base_j, slope_j}
    __shared__ float4 sUC[HID][4];      // depth-0 uniform sincos(u) for AA pairs 4..7
    __shared__ float4 sF0[HID];         // Wf1 col j, elems 0..3
    __shared__ float2 sF1[HID];         // Wf1 col j, elems 4..5
    __shared__ float4 sO0[HID];         // Ws[j][0..2], Wdir[j][0]
    __shared__ float4 sO1[HID];         // Wdir[j][1..2], Wrho[j][0..1]
    __shared__ float  sO2[HID];         // Wrho[j][2]
    __shared__ u64    sZp[8][TOT];      // packed z-pairs, [p][tid]: 8B stride -> conflict-free
    __shared__ float  red[4][3];

    int tid = threadIdx.x;
    if (tid < HID) {
        int j = tid;
        sA[j]   = make_float4(gWd1[j], gWd1[64 + j], gWd1[128 + j], 0.0f);
        sBxy[j] = make_ulonglong2(dup_bits(gWd2[j * 3]), dup_bits(gWd2[j * 3 + 1]));
        sBz[j]  = dup_bits(gWd2[j * 3 + 2]);
        sF0[j] = make_float4(gWf1[j], gWf1[64 + j], gWf1[128 + j], gWf1[192 + j]);
        sF1[j] = make_float2(gWf1[256 + j], gWf1[320 + j]);
        sO0[j] = make_float4(gWs[j * 3], gWs[j * 3 + 1], gWs[j * 3 + 2], gWdir[j * 3]);
        sO1[j] = make_float4(gWdir[j * 3 + 1], gWdir[j * 3 + 2], gWrho[j * 3], gWrho[j * 3 + 1]);
        sO2[j] = gWrho[j * 3 + 2];
    }
    __syncthreads();

    int ray = blockIdx.x;
    int m = ray * TOT + tid;

    float ox = rays_o[ray * 3 + 0], oy = rays_o[ray * 3 + 1], oz = rays_o[ray * 3 + 2];
    float dx = rays_d[ray * 3 + 0], dy = rays_d[ray * 3 + 1], dz = rays_d[ray * 3 + 2];
    bool alive = true;
    float thr0 = 1.0f, thr1 = 1.0f, thr2 = 1.0f;
    float rgb0 = 0.0f, rgb1 = 0.0f, rgb2 = 0.0f;

    // packed AA constants (dep-0 tiny-angle polys)
    u64 cone  = bc2(1.0f);
    u64 cm16  = bc2(-0.16666667f);
    u64 cmh   = bc2(-0.5f);

    #pragma unroll
    for (int dep = 0; dep < 2; ++dep) {
        // sphere intersection (needed before the dep-0 uniform tables)
        float a = dx * dx + dy * dy + dz * dz;
        float b = 2.0f * (dx * ox + dy * oy + dz * oz);
        float c = ox * ox + oy * oy + oz * oz - 1.0f;
        float delta = b * b - 4.0f * a * c;
        alive = alive && (delta > 0.0f);
        float sq = sqrtf(fmaxf(delta, 0.0f));
        float twoa = 2.0f * a;
        float nears = fmaxf((-b - sq) / twoa, 0.001f);
        float fars  = fmaxf((-b + sq) / twoa, 0.001f);
        float span = fars - nears;

        // Depth-0 block-uniform precomputes: base/slope dots, and the
        // sincos(u) table for AA pairs 4..7 (samples 8..15 on the nominal grid).
        if (dep == 0) {
            if (tid < HID) {
                float4 aa = sA[tid];
                float base  = fmaf(ox, aa.x, fmaf(oy, aa.y, oz * aa.z));
                float slope = fmaf(dx, aa.x, fmaf(dy, aa.y, dz * aa.z));
                sBS[tid] = make_float2(base, slope);
            }
            __syncthreads();
            {
                int j = tid >> 1;
                float2 bs = sBS[j];
                #pragma unroll
                for (int qq = 0; qq < 2; qq++) {
                    int q2 = ((tid & 1) << 1) + qq;   // 0..3 -> global pairs 4..7
                    int s0 = 8 + 2 * q2;
                    float u0 = fmaf(bs.y, fmaf(span, (float)(s0)     * (1.0f/15.0f), nears), bs.x);
                    float u1 = fmaf(bs.y, fmaf(span, (float)(s0 + 1) * (1.0f/15.0f), nears), bs.x);
                    sUC[j][q2] = make_float4(__sinf(u0), __sinf(u1), __cosf(u0), __cosf(u1));
                }
            }
            __syncthreads();
        }

        // ---- density over 16 jittered samples ----
        const float4* jp = (const float4*)(jitter + (size_t)dep * (size_t)MTOT * INDS
                                                  + (size_t)m * INDS);
        u64 jv[4];     // dep-0 AA: (jit-0.5)*span/16 for samples 8..15, packed
        {
            float K = span * (1.0f / 16.0f);
            #pragma unroll
            for (int q = 0; q < 4; q++) {
                float4 jvq = jp[q];
                float z0 = nears + span * ((float)(4*q + 0) * (1.0f/15.0f)) + (jvq.x - 0.5f) * K;
                float z1 = nears + span * ((float)(4*q + 1) * (1.0f/15.0f)) + (jvq.y - 0.5f) * K;
                float z2 = nears + span * ((float)(4*q + 2) * (1.0f/15.0f)) + (jvq.z - 0.5f) * K;
                float z3 = nears + span * ((float)(4*q + 3) * (1.0f/15.0f)) + (jvq.w - 0.5f) * K;
                sZp[2*q][tid]     = pk2(z0, z1);
                sZp[2*q + 1][tid] = pk2(z2, z3);
                if (q >= 2) {
                    jv[2*(q-2)]     = pk2((jvq.x - 0.5f) * K, (jvq.y - 0.5f) * K);
                    jv[2*(q-2) + 1] = pk2((jvq.z - 0.5f) * K, (jvq.w - 0.5f) * K);
                }
            }
        }

        u64 Acc[8][3];
        #pragma unroll
        for (int p = 0; p < 8; p++) { Acc[p][0] = 0; Acc[p][1] = 0; Acc[p][2] = 0; }

        if (dep == 0) {
            #pragma unroll 2
            for (int j = 0; j < HID; j++) {
                float2 bs = sBS[j];
                u64 base2  = bc2(bs.x);
                u64 slope2 = bc2(bs.y);
                ulonglong2 bxy = sBxy[j];
                u64 bz = sBz[j];
                u64 H[8];
                // pairs 0..3: MUFU sin
                #pragma unroll
                for (int p = 0; p < 4; p++)
                    H[p] = sin2_mufu(fma2(sZp[p][tid], slope2, base2));
                // pairs 4..7: angle addition, zero MUFU
                #pragma unroll
                for (int q2 = 0; q2 < 4; q2++) {
                    float4 uc = sUC[j][q2];
                    u64 su2 = pk2(uc.x, uc.y);
                    u64 cu2 = pk2(uc.z, uc.w);
                    u64 v    = mul2(jv[q2], slope2);
                    u64 s2   = mul2(v, v);
                    u64 sinv = mul2(v, fma2(s2, cm16, cone));
                    u64 cosv = fma2(s2, cmh, cone);
                    H[4 + q2] = fma2(cu2, sinv, mul2(su2, cosv));
                }
                #pragma unroll
                for (int p = 0; p < 8; p++) {
                    Acc[p][0] = fma2(H[p], bxy.x, Acc[p][0]);
                    Acc[p][1] = fma2(H[p], bxy.y, Acc[p][1]);
                    Acc[p][2] = fma2(H[p], bz,    Acc[p][2]);
                }
            }
        } else {
            #pragma unroll 2
            for (int j = 0; j < HID; j++) {
                float4 aa = sA[j];
                float base  = fmaf(ox, aa.x, fmaf(oy, aa.y, oz * aa.z));
                float slope = fmaf(dx, aa.x, fmaf(dy, aa.y, dz * aa.z));
                u64 base2  = bc2(base);
                u64 slope2 = bc2(slope);
                ulonglong2 bxy = sBxy[j];
                u64 bz = sBz[j];
                u64 H[8];
                #pragma unroll
                for (int p = 0; p < 8; p++)
                    H[p] = sin2_mufu(fma2(sZp[p][tid], slope2, base2));
                #pragma unroll
                for (int p = 0; p < 8; p++) {
                    Acc[p][0] = fma2(H[p], bxy.x, Acc[p][0]);
                    Acc[p][1] = fma2(H[p], bxy.y, Acc[p][1]);
                    Acc[p][2] = fma2(H[p], bz,    Acc[p][2]);
                }
            }
        }

        // softplus monotone -> reduce raw max per channel, softplus once.
        float rm0 = -1e30f, rm1 = -1e30f, rm2 = -1e30f;
        #pragma unroll
        for (int p = 0; p < 8; p++) {
            float pa, pb;
            upk2(Acc[p][0], pa, pb); rm0 = fmaxf(rm0, fmaxf(pa, pb));
            upk2(Acc[p][1], pa, pb); rm1 = fmaxf(rm1, fmaxf(pa, pb));
            upk2(Acc[p][2], pa, pb); rm2 = fmaxf(rm2, fmaxf(pa, pb));
        }
        float mm0 = fmaxf(softplus_fast(rm0), 0.001f);
        float mm1 = fmaxf(softplus_fast(rm1), 0.001f);
        float mm2 = fmaxf(softplus_fast(rm2), 0.001f);
        float maxm = fmaxf(mm0, fmaxf(mm1, mm2));

        int ch = 0;
        float maj = 0.001f;
        float t;
        if (dep == 0) {
            ch = channel[m];
            maj = (ch == 0) ? mm0 : ((ch == 1) ? mm1 : mm2);
            float ut = u_t[m];
            t = -log1pf(-ut) / maj + nears;   // keep accurate: decides `hit`
        } else {
            t = fars;
        }
        bool hit = alive && (t >= fars);

        float dn0 = __expf(-mm0 * span) / (maxm + EPSF) + EPSF;
        float dn1 = __expf(-mm1 * span) / (maxm + EPSF) + EPSF;
        float dn2 = __expf(-mm2 * span) / (maxm + EPSF) + EPSF;
        float dmean = (dn0 + dn1 + dn2) * (1.0f / 3.0f);

        float Le0, Le1, Le2;
        sample_env(env, fmaf(dx, fars, ox), fmaf(dy, fars, oy), fmaf(dz, fars, oz),
                   Le0, Le1, Le2);

        if (hit) {
            rgb0 += thr0 * (dn0 / dmean) * Le0;
            rgb1 += thr1 * (dn1 / dmean) * Le1;
            rgb2 += thr2 * (dn2 / dmean) * Le2;
        }
        alive = alive && !hit;

        if (dep == 0) {
            float tr0 = __expf(-mm0 * (t - nears)) / maxm;
            float tr1 = __expf(-mm1 * (t - nears)) / maxm;
            float tr2 = __expf(-mm2 * (t - nears)) / maxm;
            float den2 = (mm0 * tr0 + mm1 * tr1 + mm2 * tr2) * (1.0f / 3.0f);
            if (alive) {
                thr0 = thr0 * tr0 / den2;
                thr1 = thr1 * tr1 / den2;
                thr2 = thr2 * tr2 / den2;
                ox = fmaf(dx, t, ox);
                oy = fmaf(dy, t, oy);
                oz = fmaf(dz, t, oz);
            }
            // material MLP on [o, d] (post-update o)
            float st0 = 0.0f, st1 = 0.0f, st2 = 0.0f;
            float v0 = 0.0f, v1 = 0.0f, v2 = 0.0f;
            float rh0 = 0.0f, rh1 = 0.0f, rh2 = 0.0f;
            #pragma unroll 8
            for (int j = 0; j < HID; j++) {
                float4 w0 = sF0[j];
                float2 w1 = sF1[j];
                float u = fmaf(ox, w0.x, fmaf(oy, w0.y, fmaf(oz, w0.z,
                          fmaf(dx, w0.w, fmaf(dy, w1.x, dz * w1.y)))));
                float f = tanh_fast(u);
                float4 p0 = sO0[j];
                float4 p1 = sO1[j];
                float p2 = sO2[j];
                st0 = fmaf(f, p0.x, st0);
                st1 = fmaf(f, p0.y, st1);
                st2 = fmaf(f, p0.z, st2);
                v0  = fmaf(f, p0.w, v0);
                v1  = fmaf(f, p1.x, v1);
                v2  = fmaf(f, p1.y, v2);
                rh0 = fmaf(f, p1.z, rh0);
                rh1 = fmaf(f, p1.w, rh1);
                rh2 = fmaf(f, p2,   rh2);
            }
            st0 = softplus_fast(st0);
            st1 = softplus_fast(st1);
            st2 = softplus_fast(st2);
            float nrm = sqrtf(v0 * v0 + v1 * v1 + v2 * v2);
            float invn = 1.0f / (nrm + EPSF);
            float do0 = v0 * invn, do1 = v1 * invn, do2 = v2 * invn;
            float rho0 = sigmoid_fast(rh0), rho1 = sigmoid_fast(rh1), rho2 = sigmoid_fast(rh2);

            float stch = (ch == 0) ? st0 : ((ch == 1) ? st1 : st2);
            float sp = fminf(stch / maj, 1.0f);
            float us = u_scatter[m];
            bool sm = alive && (us < sp);
            if (sm) {
                dx = do0; dy = do1; dz = do2;
                thr0 = thr0 / (sp + EPSF) * rho0;
                thr1 = thr1 / (sp + EPSF) * rho1;
                thr2 = thr2 / (sp + EPSF) * rho2;
            } else if (alive) {
                float inv = 1.0f / (1.0f - sp + EPSF);
                thr0 *= inv; thr1 *= inv; thr2 *= inv;
            }
        }
    }

    // block reduce: mean over TOT samples of this ray
    #pragma unroll
    for (int off = 16; off > 0; off >>= 1) {
        rgb0 += __shfl_down_sync(0xffffffffu, rgb0, off);
        rgb1 += __shfl_down_sync(0xffffffffu, rgb1, off);
        rgb2 += __shfl_down_sync(0xffffffffu, rgb2, off);
    }
    if ((tid & 31) == 0) {
        red[tid >> 5][0] = rgb0;
        red[tid >> 5][1] = rgb1;
        red[tid >> 5][2] = rgb2;
    }
    __syncthreads();
    if (tid == 0) {
        float a0 = red[0][0] + red[1][0] + red[2][0] + red[3][0];
        float a1 = red[0][1] + red[1][1] + red[2][1] + red[3][1];
        float a2 = red[0][2] + red[1][2] + red[2][2] + red[3][2];
        out[ray * 3 + 0] = a0 * (1.0f / (float)TOT);
        out[ray * 3 + 1] = a1 * (1.0f / (float)TOT);
        out[ray * 3 + 2] = a2 * (1.0f / (float)TOT);
    }
}

extern "C" void kernel_launch(void* const* d_in, const int* in_sizes, int n_in,
                              void* d_out, int out_size) {
    const float* rays_o    = (const float*)d_in[0];
    const float* rays_d    = (const float*)d_in[1];
    const float* env       = (const float*)d_in[2];
    const float* Wd1       = (const float*)d_in[3];
    const float* Wd2       = (const float*)d_in[4];
    const float* Wf1       = (const float*)d_in[5];
    const float* Ws        = (const float*)d_in[6];
    const float* Wdir      = (const float*)d_in[7];
    const float* Wrho      = (const float*)d_in[8];
    const float* jitter    = (const float*)d_in[9];
    const float* u_t       = (const float*)d_in[10];
    const float* u_scatter = (const float*)d_in[11];
    const int*   channel   = (const int*)d_in[12];
    float* out = (float*)d_out;

    nerf_render_kernel<<<NRAYS, TOT>>>(rays_o, rays_d, env, Wd1, Wd2, Wf1, Ws,
                                       Wdir, Wrho, jitter, u_t, u_scatter,
                                       channel, out);
}

// round 16
// speedup vs baseline: 1.0874x; 1.0361x over previous
#include <cuda_runtime.h>
#include <math.h>

#define NRAYS 2048
#define TOT 128
#define INDS 16
#define HID 64
#define MTOT (NRAYS*TOT)
#define EPSF 1e-8f

typedef unsigned long long u64;

// ---------------- f32x2 packed helpers (sm_103a) ----------------
__device__ __forceinline__ u64 pk2(float lo, float hi) {
    u64 r; asm("mov.b64 %0, {%1,%2};" : "=l"(r) : "f"(lo), "f"(hi)); return r;
}
__device__ __forceinline__ u64 bc2(float v) {
    u64 r; asm("mov.b64 %0, {%1,%1};" : "=l"(r) : "f"(v)); return r;
}
__device__ __forceinline__ void upk2(u64 a, float& lo, float& hi) {
    asm("mov.b64 {%0,%1}, %2;" : "=f"(lo), "=f"(hi) : "l"(a));
}
__device__ __forceinline__ u64 fma2(u64 a, u64 b, u64 c) {
    u64 d; asm("fma.rn.f32x2 %0, %1, %2, %3;" : "=l"(d) : "l"(a), "l"(b), "l"(c)); return d;
}
__device__ __forceinline__ u64 mul2(u64 a, u64 b) {
    u64 d; asm("mul.rn.f32x2 %0, %1, %2;" : "=l"(d) : "l"(a), "l"(b)); return d;
}

// MUFU sin pair: 2 SFU-pipe instructions, zero FMA-pipe cost.
__device__ __forceinline__ u64 sin2_mufu(u64 x) {
    float lo, hi; upk2(x, lo, hi);
    return pk2(__sinf(lo), __sinf(hi));
}

// ---------------- scalar helpers (fast-math epilogue) ----------------
__device__ __forceinline__ float tanh_fast(float x) {
    float ax = fminf(fabsf(x), 10.0f);
    float e = __expf(2.0f * ax);
    float t = __fdividef(e - 1.0f, e + 1.0f);
    return (x < 0.0f) ? -t : t;
}
__device__ __forceinline__ float softplus_fast(float x) {
    return fmaxf(x, 0.0f) + __logf(1.0f + __expf(-fabsf(x)));
}
__device__ __forceinline__ float sigmoid_fast(float x) {
    float e = __expf(-fabsf(x));
    float r = __fdividef(1.0f, 1.0f + e);
    return (x >= 0.0f) ? r : (1.0f - r);
}

// fast atan2: deg-17 odd minimax on [0,1] + quadrant fixup. abs err ~1e-7.
// Matches numpy semantics incl. atan2(0,0)=0 (q=0/0 -> NaN -> 0 fixup).
__device__ __forceinline__ float fast_atan2(float y, float x) {
    float ax = fabsf(x), ay = fabsf(y);
    float mx = fmaxf(ax, ay), mn = fminf(ax, ay);
    float q = __fdividef(mn, mx);
    float s = q * q;
    float p =              0.00286623f;
    p = fmaf(p, s, -0.0161657f);
    p = fmaf(p, s,  0.0429096f);
    p = fmaf(p, s, -0.0752896f);
    p = fmaf(p, s,  0.106563f);
    p = fmaf(p, s, -0.142089f);
    p = fmaf(p, s,  0.199936f);
    p = fmaf(p, s, -0.333331f);
    float r = fmaf(p * s, q, q);
    if (ay > ax) r = 1.57079632679f - r;
    if (x < 0.0f) r = 3.14159265359f - r;
    r = (y < 0.0f) ? -r : r;
    if (isnan(r)) r = 0.0f;
    return r;
}

// ---------------- env map bilinear sample ----------------
__device__ __forceinline__ void sample_env(const float* __restrict__ env,
                                           float px, float py, float pz,
                                           float& Le0, float& Le1, float& Le2) {
    const float INV_PI = 0.3183098861837907f;
    float theta = fast_atan2(px, -pz) * INV_PI;
    // acos(py) = atan2(sqrt(1-py^2), py); py<-1 (float rounding past the
    // pole) must map to 0 to match nan_to_num(acos(NaN)).
    float w2 = fmaxf(1.0f - py * py, 0.0f);
    float ac = fast_atan2(sqrtf(w2), py);
    if (py < -1.0f) ac = 0.0f;
    float phi = fmaf(ac, 2.0f * INV_PI, -1.0f);

    float ix = ((theta + 1.0f) * 256.0f - 1.0f) * 0.5f;
    float iy = ((phi   + 1.0f) * 128.0f - 1.0f) * 0.5f;
    float x0 = floorf(ix), y0 = floorf(iy);
    float wx = ix - x0,    wy = iy - y0;

    float v0 = 0.0f, v1 = 0.0f, v2 = 0.0f;
    #pragma unroll
    for (int t = 0; t < 4; t++) {
        float xc = x0 + (float)(t & 1);
        float yc = y0 + (float)(t >> 1);
        float w = ((t & 1) ? wx : (1.0f - wx)) * ((t >> 1) ? wy : (1.0f - wy));
        bool inb = (xc >= 0.0f) && (xc < 256.0f) && (yc >= 0.0f) && (yc < 128.0f);
        float wi = inb ? w : 0.0f;
        int xi = (int)fminf(fmaxf(xc, 0.0f), 255.0f);
        int yi = (int)fminf(fmaxf(yc, 0.0f), 127.0f);
        int base = yi * 256 + xi;
        v0 = fmaf(wi, env[base],         v0);
        v1 = fmaf(wi, env[32768 + base], v1);
        v2 = fmaf(wi, env[65536 + base], v2);
    }
    Le0 = __expf(v0); Le1 = __expf(v1); Le2 = __expf(v2);
}

__device__ __forceinline__ u64 dup_bits(float v) {
    u64 b = (u64)__float_as_uint(v);
    return b | (b << 32);
}

// ---------------- main fused renderer: 1 block = 1 ray, 1 thread = 1 sample ----------------
// Density (R13 structure): dep-0 = 6 MUFU + 2 angle-addition pairs, dep-1
// all-MUFU, unroll-2 software pipelining, z-pairs in smem. Material MLP
// packed in f32x2 (pairs j,j+1). Fast env trig.
__global__ __launch_bounds__(TOT, 4)
void nerf_render_kernel(
    const float* __restrict__ rays_o, const float* __restrict__ rays_d,
    const float* __restrict__ env,
    const float* __restrict__ gWd1, const float* __restrict__ gWd2,
    const float* __restrict__ gWf1, const float* __restrict__ gWs,
    const float* __restrict__ gWdir, const float* __restrict__ gWrho,
    const float* __restrict__ jitter, const float* __restrict__ u_t,
    const float* __restrict__ u_scatter, const int* __restrict__ channel,
    float* __restrict__ out)
{
    __shared__ float4 sA[HID];          // Wd1 col j: ax, ay, az, 0
    __shared__ ulonglong2 sBxy[HID];    // Wd2 row j: bx dup, by dup
    __shared__ u64 sBz[HID];            // Wd2 row j: bz dup
    __shared__ float2 sBS[HID];         // depth-0 block-uniform {base_j, slope_j}
    __shared__ float4 sUC[HID][2];      // depth-0 uniform sincos(u) for AA pairs 6,7
    __shared__ float4 sF0[HID];         // Wf1 col j, elems 0..3
    __shared__ float2 sF1[HID];         // Wf1 col j, elems 4..5
    __shared__ ulonglong2 sMPa[HID/2];  // packed {Ws0(j,j+1), Ws1(j,j+1)}
    __shared__ ulonglong2 sMPb[HID/2];  // packed {Ws2, Wdir0}
    __shared__ ulonglong2 sMPc[HID/2];  // packed {Wdir1, Wdir2}
    __shared__ ulonglong2 sMPd[HID/2];  // packed {Wrho0, Wrho1}
    __shared__ u64        sMPe[HID/2];  // packed {Wrho2}
    __shared__ u64    sZp[8][TOT];      // packed z-pairs, [p][tid]
    __shared__ float  red[4][3];

    int tid = threadIdx.x;
    if (tid < HID) {
        int j = tid;
        sA[j]   = make_float4(gWd1[j], gWd1[64 + j], gWd1[128 + j], 0.0f);
        sBxy[j] = make_ulonglong2(dup_bits(gWd2[j * 3]), dup_bits(gWd2[j * 3 + 1]));
        sBz[j]  = dup_bits(gWd2[j * 3 + 2]);
        sF0[j] = make_float4(gWf1[j], gWf1[64 + j], gWf1[128 + j], gWf1[192 + j]);
        sF1[j] = make_float2(gWf1[256 + j], gWf1[320 + j]);
    }
    if (tid < HID / 2) {
        int jj = tid;
        int a = 6 * jj, b = 6 * jj + 3;
        sMPa[jj] = make_ulonglong2(pk2(gWs[a],     gWs[b]),     pk2(gWs[a + 1],   gWs[b + 1]));
        sMPb[jj] = make_ulonglong2(pk2(gWs[a + 2], gWs[b + 2]), pk2(gWdir[a],     gWdir[b]));
        sMPc[jj] = make_ulonglong2(pk2(gWdir[a + 1], gWdir[b + 1]), pk2(gWdir[a + 2], gWdir[b + 2]));
        sMPd[jj] = make_ulonglong2(pk2(gWrho[a],   gWrho[b]),   pk2(gWrho[a + 1], gWrho[b + 1]));
        sMPe[jj] = pk2(gWrho[a + 2], gWrho[b + 2]);
    }
    __syncthreads();

    int ray = blockIdx.x;
    int m = ray * TOT + tid;

    float ox = rays_o[ray * 3 + 0], oy = rays_o[ray * 3 + 1], oz = rays_o[ray * 3 + 2];
    float dx = rays_d[ray * 3 + 0], dy = rays_d[ray * 3 + 1], dz = rays_d[ray * 3 + 2];
    bool alive = true;
    float thr0 = 1.0f, thr1 = 1.0f, thr2 = 1.0f;
    float rgb0 = 0.0f, rgb1 = 0.0f, rgb2 = 0.0f;

    // packed AA constants (dep-0 tiny-angle polys)
    u64 cone  = bc2(1.0f);
    u64 cm16  = bc2(-0.16666667f);
    u64 cmh   = bc2(-0.5f);

    #pragma unroll
    for (int dep = 0; dep < 2; ++dep) {
        // sphere intersection
        float a = dx * dx + dy * dy + dz * dz;
        float b = 2.0f * (dx * ox + dy * oy + dz * oz);
        float c = ox * ox + oy * oy + oz * oz - 1.0f;
        float delta = b * b - 4.0f * a * c;
        alive = alive && (delta > 0.0f);
        float sq = sqrtf(fmaxf(delta, 0.0f));
        float twoa = 2.0f * a;
        float nears = fmaxf((-b - sq) / twoa, 0.001f);
        float fars  = fmaxf((-b + sq) / twoa, 0.001f);
        float span = fars - nears;

        // Depth-0 block-uniform precomputes
        if (dep == 0) {
            if (tid < HID) {
                float4 aa = sA[tid];
                float base  = fmaf(ox, aa.x, fmaf(oy, aa.y, oz * aa.z));
                float slope = fmaf(dx, aa.x, fmaf(dy, aa.y, dz * aa.z));
                sBS[tid] = make_float2(base, slope);
            }
            __syncthreads();
            {
                int j = tid >> 1;
                int q2 = tid & 1;                  // 0 -> pair 6, 1 -> pair 7
                float2 bs = sBS[j];
                int s0 = 12 + 2 * q2;
                float u0 = fmaf(bs.y, fmaf(span, (float)(s0)     * (1.0f/15.0f), nears), bs.x);
                float u1 = fmaf(bs.y, fmaf(span, (float)(s0 + 1) * (1.0f/15.0f), nears), bs.x);
                sUC[j][q2] = make_float4(__sinf(u0), __sinf(u1), __cosf(u0), __cosf(u1));
            }
            __syncthreads();
        }

        // ---- density over 16 jittered samples ----
        const float4* jp = (const float4*)(jitter + (size_t)dep * (size_t)MTOT * INDS
                                                  + (size_t)m * INDS);
        u64 jv[2];     // dep-0 AA: (jit-0.5)*span/16 for samples 12..15, packed
        {
            float K = span * (1.0f / 16.0f);
            #pragma unroll
            for (int q = 0; q < 4; q++) {
                float4 jvq = jp[q];
                if (q == 3 && dep == 0) {
                    // AA pairs: only the jitter offsets are needed
                    jv[0] = pk2((jvq.x - 0.5f) * K, (jvq.y - 0.5f) * K);
                    jv[1] = pk2((jvq.z - 0.5f) * K, (jvq.w - 0.5f) * K);
                } else {
                    float z0 = nears + span * ((float)(4*q + 0) * (1.0f/15.0f)) + (jvq.x - 0.5f) * K;
                    float z1 = nears + span * ((float)(4*q + 1) * (1.0f/15.0f)) + (jvq.y - 0.5f) * K;
                    float z2 = nears + span * ((float)(4*q + 2) * (1.0f/15.0f)) + (jvq.z - 0.5f) * K;
                    float z3 = nears + span * ((float)(4*q + 3) * (1.0f/15.0f)) + (jvq.w - 0.5f) * K;
                    sZp[2*q][tid]     = pk2(z0, z1);
                    sZp[2*q + 1][tid] = pk2(z2, z3);
                }
            }
        }

        u64 Acc[8][3];
        #pragma unroll
        for (int p = 0; p < 8; p++) { Acc[p][0] = 0; Acc[p][1] = 0; Acc[p][2] = 0; }

        if (dep == 0) {
            #pragma unroll 2
            for (int j = 0; j < HID; j++) {
                float2 bs = sBS[j];
                u64 base2  = bc2(bs.x);
                u64 slope2 = bc2(bs.y);
                ulonglong2 bxy = sBxy[j];
                u64 bz = sBz[j];
                u64 H[8];
                #pragma unroll
                for (int p = 0; p < 6; p++)
                    H[p] = sin2_mufu(fma2(sZp[p][tid], slope2, base2));
                #pragma unroll
                for (int q2 = 0; q2 < 2; q2++) {
                    float4 uc = sUC[j][q2];
                    u64 su2 = pk2(uc.x, uc.y);
                    u64 cu2 = pk2(uc.z, uc.w);
                    u64 v    = mul2(jv[q2], slope2);
                    u64 s2   = mul2(v, v);
                    u64 sinv = mul2(v, fma2(s2, cm16, cone));
                    u64 cosv = fma2(s2, cmh, cone);
                    H[6 + q2] = fma2(cu2, sinv, mul2(su2, cosv));
                }
                #pragma unroll
                for (int p = 0; p < 8; p++) {
                    Acc[p][0] = fma2(H[p], bxy.x, Acc[p][0]);
                    Acc[p][1] = fma2(H[p], bxy.y, Acc[p][1]);
                    Acc[p][2] = fma2(H[p], bz,    Acc[p][2]);
                }
            }
        } else {
            #pragma unroll 2
            for (int j = 0; j < HID; j++) {
                float4 aa = sA[j];
                float base  = fmaf(ox, aa.x, fmaf(oy, aa.y, oz * aa.z));
                float slope = fmaf(dx, aa.x, fmaf(dy, aa.y, dz * aa.z));
                u64 base2  = bc2(base);
                u64 slope2 = bc2(slope);
                ulonglong2 bxy = sBxy[j];
                u64 bz = sBz[j];
                u64 H[8];
                #pragma unroll
                for (int p = 0; p < 8; p++)
                    H[p] = sin2_mufu(fma2(sZp[p][tid], slope2, base2));
                #pragma unroll
                for (int p = 0; p < 8; p++) {
                    Acc[p][0] = fma2(H[p], bxy.x, Acc[p][0]);
                    Acc[p][1] = fma2(H[p], bxy.y, Acc[p][1]);
                    Acc[p][2] = fma2(H[p], bz,    Acc[p][2]);
                }
            }
        }

        // softplus monotone -> reduce raw max per channel, softplus once.
        float rm0 = -1e30f, rm1 = -1e30f, rm2 = -1e30f;
        #pragma unroll
        for (int p = 0; p < 8; p++) {
            float pa, pb;
            upk2(Acc[p][0], pa, pb); rm0 = fmaxf(rm0, fmaxf(pa, pb));
            upk2(Acc[p][1], pa, pb); rm1 = fmaxf(rm1, fmaxf(pa, pb));
            upk2(Acc[p][2], pa, pb); rm2 = fmaxf(rm2, fmaxf(pa, pb));
        }
        float mm0 = fmaxf(softplus_fast(rm0), 0.001f);
        float mm1 = fmaxf(softplus_fast(rm1), 0.001f);
        float mm2 = fmaxf(softplus_fast(rm2), 0.001f);
        float maxm = fmaxf(mm0, fmaxf(mm1, mm2));

        int ch = 0;
        float maj = 0.001f;
        float t;
        if (dep == 0) {
            ch = channel[m];
            maj = (ch == 0) ? mm0 : ((ch == 1) ? mm1 : mm2);
            float ut = u_t[m];
            t = __logf(1.0f - ut) / (-maj) + nears;
        } else {
            t = fars;
        }
        bool hit = alive && (t >= fars);

        float dn0 = __expf(-mm0 * span) / (maxm + EPSF) + EPSF;
        float dn1 = __expf(-mm1 * span) / (maxm + EPSF) + EPSF;
        float dn2 = __expf(-mm2 * span) / (maxm + EPSF) + EPSF;
        float dmean = (dn0 + dn1 + dn2) * (1.0f / 3.0f);

        float Le0, Le1, Le2;
        sample_env(env, fmaf(dx, fars, ox), fmaf(dy, fars, oy), fmaf(dz, fars, oz),
                   Le0, Le1, Le2);

        if (hit) {
            rgb0 += thr0 * (dn0 / dmean) * Le0;
            rgb1 += thr1 * (dn1 / dmean) * Le1;
            rgb2 += thr2 * (dn2 / dmean) * Le2;
        }
        alive = alive && !hit;

        if (dep == 0) {
            float tr0 = __expf(-mm0 * (t - nears)) / maxm;
            float tr1 = __expf(-mm1 * (t - nears)) / maxm;
            float tr2 = __expf(-mm2 * (t - nears)) / maxm;
            float den2 = (mm0 * tr0 + mm1 * tr1 + mm2 * tr2) * (1.0f / 3.0f);
            if (alive) {
                thr0 = thr0 * tr0 / den2;
                thr1 = thr1 * tr1 / den2;
                thr2 = thr2 * tr2 / den2;
                ox = fmaf(dx, t, ox);
                oy = fmaf(dy, t, oy);
                oz = fmaf(dz, t, oz);
            }
            // material MLP on [o, d] (post-update o), f32x2-packed over j pairs
            u64 aS0 = 0, aS1 = 0, aS2 = 0;
            u64 aV0 = 0, aV1 = 0, aV2 = 0;
            u64 aR0 = 0, aR1 = 0, aR2 = 0;
            #pragma unroll 4
            for (int jj = 0; jj < HID / 2; jj++) {
                int j = 2 * jj;
                float4 w0a = sF0[j];     float2 w1a = sF1[j];
                float4 w0b = sF0[j + 1]; float2 w1b = sF1[j + 1];
                float ua = fmaf(ox, w0a.x, fmaf(oy, w0a.y, fmaf(oz, w0a.z,
                           fmaf(dx, w0a.w, fmaf(dy, w1a.x, dz * w1a.y)))));
                float ub = fmaf(ox, w0b.x, fmaf(oy, w0b.y, fmaf(oz, w0b.z,
                           fmaf(dx, w0b.w, fmaf(dy, w1b.x, dz * w1b.y)))));
                u64 f2 = pk2(tanh_fast(ua), tanh_fast(ub));
                ulonglong2 ma = sMPa[jj];
                ulonglong2 mb = sMPb[jj];
                ulonglong2 mc = sMPc[jj];
                ulonglong2 md = sMPd[jj];
                u64 me = sMPe[jj];
                aS0 = fma2(f2, ma.x, aS0); aS1 = fma2(f2, ma.y, aS1);
                aS2 = fma2(f2, mb.x, aS2); aV0 = fma2(f2, mb.y, aV0);
                aV1 = fma2(f2, mc.x, aV1); aV2 = fma2(f2, mc.y, aV2);
                aR0 = fma2(f2, md.x, aR0); aR1 = fma2(f2, md.y, aR1);
                aR2 = fma2(f2, me, aR2);
            }
            float lo, hi;
            upk2(aS0, lo, hi); float st0 = lo + hi;
            upk2(aS1, lo, hi); float st1 = lo + hi;
            upk2(aS2, lo, hi); float st2 = lo + hi;
            upk2(aV0, lo, hi); float v0 = lo + hi;
            upk2(aV1, lo, hi); float v1 = lo + hi;
            upk2(aV2, lo, hi); float v2 = lo + hi;
            upk2(aR0, lo, hi); float rh0 = lo + hi;
            upk2(aR1, lo, hi); float rh1 = lo + hi;
            upk2(aR2, lo, hi); float rh2 = lo + hi;

            st0 = softplus_fast(st0);
            st1 = softplus_fast(st1);
            st2 = softplus_fast(st2);
            float nrm = sqrtf(v0 * v0 + v1 * v1 + v2 * v2);
            float invn = 1.0f / (nrm + EPSF);
            float do0 = v0 * invn, do1 = v1 * invn, do2 = v2 * invn;
            float rho0 = sigmoid_fast(rh0), rho1 = sigmoid_fast(rh1), rho2 = sigmoid_fast(rh2);

            float stch = (ch == 0) ? st0 : ((ch == 1) ? st1 : st2);
            float sp = fminf(stch / maj, 1.0f);
            float us = u_scatter[m];
            bool sm = alive && (us < sp);
            if (sm) {
                dx = do0; dy = do1; dz = do2;
                thr0 = thr0 / (sp + EPSF) * rho0;
                thr1 = thr1 / (sp + EPSF) * rho1;
                thr2 = thr2 / (sp + EPSF) * rho2;
            } else if (alive) {
                float inv = 1.0f / (1.0f - sp + EPSF);
                thr0 *= inv; thr1 *= inv; thr2 *= inv;
            }
        }
    }

    // block reduce: mean over TOT samples of this ray
    #pragma unroll
    for (int off = 16; off > 0; off >>= 1) {
        rgb0 += __shfl_down_sync(0xffffffffu, rgb0, off);
        rgb1 += __shfl_down_sync(0xffffffffu, rgb1, off);
        rgb2 += __shfl_down_sync(0xffffffffu, rgb2, off);
    }
    if ((tid & 31) == 0) {
        red[tid >> 5][0] = rgb0;
        red[tid >> 5][1] = rgb1;
        red[tid >> 5][2] = rgb2;
    }
    __syncthreads();
    if (tid == 0) {
        float a0 = red[0][0] + red[1][0] + red[2][0] + red[3][0];
        float a1 = red[0][1] + red[1][1] + red[2][1] + red[3][1];
        float a2 = red[0][2] + red[1][2] + red[2][2] + red[3][2];
        out[ray * 3 + 0] = a0 * (1.0f / (float)TOT);
        out[ray * 3 + 1] = a1 * (1.0f / (float)TOT);
        out[ray * 3 + 2] = a2 * (1.0f / (float)TOT);
    }
}

extern "C" void kernel_launch(void* const* d_in, const int* in_sizes, int n_in,
                              void* d_out, int out_size) {
    const float* rays_o    = (const float*)d_in[0];
    const float* rays_d    = (const float*)d_in[1];
    const float* env       = (const float*)d_in[2];
    const float* Wd1       = (const float*)d_in[3];
    const float* Wd2       = (const float*)d_in[4];
    const float* Wf1       = (const float*)d_in[5];
    const float* Ws        = (const float*)d_in[6];
    const float* Wdir      = (const float*)d_in[7];
    const float* Wrho      = (const float*)d_in[8];
    const float* jitter    = (const float*)d_in[9];
    const float* u_t       = (const float*)d_in[10];
    const float* u_scatter = (const float*)d_in[11];
    const int*   channel   = (const int*)d_in[12];
    float* out = (float*)d_out;

    nerf_render_kernel<<<NRAYS, TOT>>>(rays_o, rays_d, env, Wd1, Wd2, Wf1, Ws,
                                       Wdir, Wrho, jitter, u_t, u_scatter,
                                       channel, out);
}